// round 1
// baseline (speedup 1.0000x reference)
#include <cuda_runtime.h>

#define N_NODES 50000
#define N_EDGES 800000

// ---------------- scratch (static device globals; no allocation) ----------------
static __device__ float  g_agg[(size_t)N_NODES * 128];
static __device__ float  g_deg[N_NODES];
static __device__ float  g_y1 [(size_t)N_NODES * 256];
static __device__ float  g_t1 [(size_t)N_NODES * 512];
static __device__ float  g_h2 [(size_t)N_NODES * 256];
static __device__ float  g_p  [(size_t)N_NODES * 128];
static __device__ float  g_r2 [(size_t)N_NODES * 128];
static __device__ float  g_y2 [(size_t)N_NODES * 128];
static __device__ float  g_t3 [(size_t)N_NODES * 256];
static __device__ double g_sums[4];    // [0,1]: stage1 sum/sumsq, [2,3]: stage2
static __device__ float  g_stats[4];   // mu1, rsigma1, mu2, rsigma2
static __device__ int    g_is64;

// ---------------- init: edge dtype detect + zero reduction accumulators ----------------
__global__ void k_init(const unsigned long long* __restrict__ ei)
{
    // int64 edge indices (< 50000, >= 0) have zero high words; int32 data read as
    // u64 has the next index in the high word (nonzero w.p. ~1-2e-5 each).
    int ok = 1;
#pragma unroll
    for (int i = 0; i < 16; i++)
        ok &= ((ei[i] >> 32) == 0ull) ? 1 : 0;
    g_is64 = ok;
    g_sums[0] = 0.0; g_sums[1] = 0.0; g_sums[2] = 0.0; g_sums[3] = 0.0;
}

__global__ void k_zerof(float* __restrict__ p, int n)
{
    int i = blockIdx.x * blockDim.x + threadIdx.x;
    if (i < n) p[i] = 0.0f;
}

// ---------------- edge scatter: warp per edge, float4 vector-RED per lane ----------------
__global__ void k_scatter(const void* __restrict__ ei, const float* __restrict__ feat,
                          float* __restrict__ agg, float* __restrict__ deg, int addDeg)
{
    int gw   = (blockIdx.x * blockDim.x + threadIdx.x) >> 5;
    int lane = threadIdx.x & 31;
    if (gw >= N_EDGES) return;

    long long s, d;
    if (g_is64) {
        const long long* p = (const long long*)ei;
        s = p[gw]; d = p[N_EDGES + gw];
    } else {
        const int* p = (const int*)ei;
        s = p[gw];  d = p[N_EDGES + gw];
    }

    float4 v = reinterpret_cast<const float4*>(feat + s * 128)[lane];
    float* dp = agg + d * 128 + lane * 4;
    asm volatile("red.global.add.v4.f32 [%0], {%1,%2,%3,%4};"
                 :: "l"(dp), "f"(v.x), "f"(v.y), "f"(v.z), "f"(v.w) : "memory");
    if (addDeg && lane == 0) atomicAdd(deg + d, 1.0f);
}

// ---------------- generic fused SGEMM: 128x128 tile, BK=16, 256 thr, 8x8 microtile ----------------
// AMODE 0: plain A[M,K]
// AMODE 1: conv1 dual-A (k<128: agg*inv_deg from A; else x from A2), dual-B (Wl / Wr), K=256 virtual
// AMODE 2: A' = relu((A - mu) * rsigma * lnw[k] + lnb[k])   (graph-LN + ReLU fused into A load)
template <int AMODE, bool RELU, bool BIAS, bool STATS>
__global__ void __launch_bounds__(256, 2)
k_gemm(const float* __restrict__ A, const float* __restrict__ A2,
       const float* __restrict__ B, const float* __restrict__ B2,
       const float* __restrict__ bias, float* __restrict__ C,
       int M, int Nc, int K,
       const float* __restrict__ deg,
       const float* __restrict__ lnw, const float* __restrict__ lnb,
       const float* __restrict__ stats, double* __restrict__ sums)
{
    __shared__ float  As[16][128];
    __shared__ float  Bs[16][128];
    __shared__ double sred[256];

    const int tid = threadIdx.x;
    const int tx = tid & 15;   // col group
    const int ty = tid >> 4;   // row group
    const int rowBase = blockIdx.y * 128;
    const int colBase = blockIdx.x * 128;

    float mu = 0.f, rs = 0.f;
    if (AMODE == 2) { mu = stats[0]; rs = stats[1]; }

    float acc[8][8];
#pragma unroll
    for (int i = 0; i < 8; i++)
#pragma unroll
        for (int j = 0; j < 8; j++) acc[i][j] = 0.f;

    const int aRow  = tid >> 2;         // 0..63
    const int aCol4 = (tid & 3) * 4;    // 0,4,8,12
    const int bRow  = tid >> 5;         // 0..7
    const int bCol  = (tid & 31) * 4;   // 0..124

    for (int k0 = 0; k0 < K; k0 += 16) {
        // ---- A tile (with per-mode transform) ----
#pragma unroll
        for (int rr = 0; rr < 2; rr++) {
            int r = aRow + rr * 64;
            int grow = rowBase + r;
            float4 v = make_float4(0.f, 0.f, 0.f, 0.f);
            if (grow < M) {
                int k = k0 + aCol4;
                if (AMODE == 1) {
                    if (k < 128) {
                        v = *reinterpret_cast<const float4*>(A + grow * 128 + k);
                        float inv = 1.0f / fmaxf(deg[grow], 1.0f);
                        v.x *= inv; v.y *= inv; v.z *= inv; v.w *= inv;
                    } else {
                        v = *reinterpret_cast<const float4*>(A2 + grow * 128 + (k - 128));
                    }
                } else {
                    v = *reinterpret_cast<const float4*>(A + grow * K + k);
                    if (AMODE == 2) {
                        float4 w4 = *reinterpret_cast<const float4*>(lnw + k);
                        float4 b4 = *reinterpret_cast<const float4*>(lnb + k);
                        v.x = fmaxf((v.x - mu) * rs * w4.x + b4.x, 0.f);
                        v.y = fmaxf((v.y - mu) * rs * w4.y + b4.y, 0.f);
                        v.z = fmaxf((v.z - mu) * rs * w4.z + b4.z, 0.f);
                        v.w = fmaxf((v.w - mu) * rs * w4.w + b4.w, 0.f);
                    }
                }
            }
            As[aCol4 + 0][r] = v.x;
            As[aCol4 + 1][r] = v.y;
            As[aCol4 + 2][r] = v.z;
            As[aCol4 + 3][r] = v.w;
        }
        // ---- B tile ----
#pragma unroll
        for (int rr = 0; rr < 2; rr++) {
            int kr = bRow + rr * 8;
            int k = k0 + kr;
            const float* Bp = B;
            int kk = k;
            if (AMODE == 1) { if (k >= 128) { Bp = B2; kk = k - 128; } }
            float4 v = *reinterpret_cast<const float4*>(Bp + kk * Nc + colBase + bCol);
            *reinterpret_cast<float4*>(&Bs[kr][bCol]) = v;
        }
        __syncthreads();

#pragma unroll
        for (int k = 0; k < 16; k++) {
            float a[8], b[8];
            *reinterpret_cast<float4*>(&a[0]) = *reinterpret_cast<float4*>(&As[k][ty * 8]);
            *reinterpret_cast<float4*>(&a[4]) = *reinterpret_cast<float4*>(&As[k][ty * 8 + 4]);
            *reinterpret_cast<float4*>(&b[0]) = *reinterpret_cast<float4*>(&Bs[k][tx * 8]);
            *reinterpret_cast<float4*>(&b[4]) = *reinterpret_cast<float4*>(&Bs[k][tx * 8 + 4]);
#pragma unroll
            for (int i = 0; i < 8; i++)
#pragma unroll
                for (int j = 0; j < 8; j++)
                    acc[i][j] += a[i] * b[j];
        }
        __syncthreads();
    }

    // ---- epilogue ----
    float bi[8];
    if (BIAS) {
        *reinterpret_cast<float4*>(&bi[0]) = *reinterpret_cast<const float4*>(bias + colBase + tx * 8);
        *reinterpret_cast<float4*>(&bi[4]) = *reinterpret_cast<const float4*>(bias + colBase + tx * 8 + 4);
    }
    double s1 = 0.0, s2 = 0.0;
#pragma unroll
    for (int i = 0; i < 8; i++) {
        int grow = rowBase + ty * 8 + i;
        if (grow < M) {
            float outv[8];
#pragma unroll
            for (int j = 0; j < 8; j++) {
                float c = acc[i][j];
                if (BIAS) c += bi[j];
                if (RELU) c = fmaxf(c, 0.f);
                outv[j] = c;
                if (STATS) { s1 += (double)c; s2 += (double)c * (double)c; }
            }
            float4* cp = reinterpret_cast<float4*>(C + (size_t)grow * Nc + colBase + tx * 8);
            cp[0] = make_float4(outv[0], outv[1], outv[2], outv[3]);
            cp[1] = make_float4(outv[4], outv[5], outv[6], outv[7]);
        }
    }

    if (STATS) {
        sred[tid] = s1; __syncthreads();
        for (int o = 128; o > 0; o >>= 1) { if (tid < o) sred[tid] += sred[tid + o]; __syncthreads(); }
        if (tid == 0) atomicAdd(&sums[0], sred[0]);
        __syncthreads();
        sred[tid] = s2; __syncthreads();
        for (int o = 128; o > 0; o >>= 1) { if (tid < o) sred[tid] += sred[tid + o]; __syncthreads(); }
        if (tid == 0) atomicAdd(&sums[1], sred[0]);
    }
}

// ---------------- conv2 combine: y2 = agg/deg + bl2 + r2, with global stats ----------------
__global__ void k_y2(const float* __restrict__ agg, const float* __restrict__ r2,
                     const float* __restrict__ bl2, const float* __restrict__ deg,
                     float* __restrict__ y2)
{
    __shared__ double sred[256];
    double s1 = 0.0, s2 = 0.0;
    const int n = N_NODES * 128;
    for (int idx = blockIdx.x * blockDim.x + threadIdx.x; idx < n; idx += gridDim.x * blockDim.x) {
        int i = idx >> 7, c = idx & 127;
        float y = agg[idx] / fmaxf(deg[i], 1.0f) + bl2[c] + r2[idx];
        y2[idx] = y;
        s1 += (double)y; s2 += (double)y * (double)y;
    }
    int tid = threadIdx.x;
    sred[tid] = s1; __syncthreads();
    for (int o = 128; o > 0; o >>= 1) { if (tid < o) sred[tid] += sred[tid + o]; __syncthreads(); }
    if (tid == 0) atomicAdd(&g_sums[2], sred[0]);
    __syncthreads();
    sred[tid] = s2; __syncthreads();
    for (int o = 128; o > 0; o >>= 1) { if (tid < o) sred[tid] += sred[tid + o]; __syncthreads(); }
    if (tid == 0) atomicAdd(&g_sums[3], sred[0]);
}

__global__ void k_finalize(int stage)
{
    double cnt = (stage == 0) ? (double)N_NODES * 256.0 : (double)N_NODES * 128.0;
    int o = stage * 2;
    double mu  = g_sums[o] / cnt;
    double var = g_sums[o + 1] / cnt - mu * mu;
    g_stats[o]     = (float)mu;
    g_stats[o + 1] = (float)(1.0 / sqrt(var + 1e-5));
}

// ---------------- launch ----------------
extern "C" void kernel_launch(void* const* d_in, const int* in_sizes, int n_in,
                              void* d_out, int out_size)
{
    const float* x    = (const float*)d_in[0];
    const void*  ei   =               d_in[1];
    const float* Wl1  = (const float*)d_in[2];
    const float* bl1  = (const float*)d_in[3];
    const float* Wr1  = (const float*)d_in[4];
    const float* ln1w = (const float*)d_in[5];
    const float* ln1b = (const float*)d_in[6];
    const float* W1   = (const float*)d_in[7];
    const float* b1   = (const float*)d_in[8];
    const float* W2   = (const float*)d_in[9];
    const float* b2   = (const float*)d_in[10];
    const float* Wl2  = (const float*)d_in[11];
    const float* bl2  = (const float*)d_in[12];
    const float* Wr2  = (const float*)d_in[13];
    const float* ln2w = (const float*)d_in[14];
    const float* ln2b = (const float*)d_in[15];
    const float* W3   = (const float*)d_in[16];
    const float* b3   = (const float*)d_in[17];
    const float* W4   = (const float*)d_in[18];
    const float* b4   = (const float*)d_in[19];
    float* out = (float*)d_out;

    float *agg, *deg, *y1, *t1, *h2, *p, *r2, *y2, *t3, *stats;
    double* sums;
    cudaGetSymbolAddress((void**)&agg,  g_agg);
    cudaGetSymbolAddress((void**)&deg,  g_deg);
    cudaGetSymbolAddress((void**)&y1,   g_y1);
    cudaGetSymbolAddress((void**)&t1,   g_t1);
    cudaGetSymbolAddress((void**)&h2,   g_h2);
    cudaGetSymbolAddress((void**)&p,    g_p);
    cudaGetSymbolAddress((void**)&r2,   g_r2);
    cudaGetSymbolAddress((void**)&y2,   g_y2);
    cudaGetSymbolAddress((void**)&t3,   g_t3);
    cudaGetSymbolAddress((void**)&sums, g_sums);
    cudaGetSymbolAddress((void**)&stats, g_stats);

    const int M = N_NODES;
    const dim3 gRows((unsigned)1, (unsigned)((M + 127) / 128));
    dim3 g1(2, gRows.y), g2(4, gRows.y), g3(2, gRows.y), g4(1, gRows.y);
    const int scatterBlocks = (N_EDGES * 32 + 255) / 256;

    // --- conv1 ---
    k_init<<<1, 1>>>((const unsigned long long*)ei);
    k_zerof<<<(N_NODES * 128 + 255) / 256, 256>>>(agg, N_NODES * 128);
    k_zerof<<<(N_NODES + 255) / 256, 256>>>(deg, N_NODES);
    k_scatter<<<scatterBlocks, 256>>>(ei, x, agg, deg, 1);
    // y1 = (agg/deg)@Wl1 + bl1 + x@Wr1, + global stats for LN1
    k_gemm<1, false, true, true><<<g1, 256>>>(agg, x, Wl1, Wr1, bl1, y1,
                                              M, 256, 256, deg, nullptr, nullptr, nullptr, sums);
    k_finalize<<<1, 1>>>(0);
    // t1 = relu(LN1(y1) @ W1 + b1)    [LN+relu fused into A load]
    k_gemm<2, true, true, false><<<g2, 256>>>(y1, nullptr, W1, nullptr, b1, t1,
                                              M, 512, 256, nullptr, ln1w, ln1b, stats + 0, nullptr);
    // h2 = relu(t1 @ W2 + b2)
    k_gemm<0, true, true, false><<<g3, 256>>>(t1, nullptr, W2, nullptr, b2, h2,
                                              M, 256, 512, nullptr, nullptr, nullptr, nullptr, nullptr);

    // --- conv2 (projected-first aggregation: agg(h)@Wl2 == agg(h@Wl2)) ---
    k_gemm<0, false, false, false><<<g4, 256>>>(h2, nullptr, Wl2, nullptr, nullptr, p,
                                                M, 128, 256, nullptr, nullptr, nullptr, nullptr, nullptr);
    k_gemm<0, false, false, false><<<g4, 256>>>(h2, nullptr, Wr2, nullptr, nullptr, r2,
                                                M, 128, 256, nullptr, nullptr, nullptr, nullptr, nullptr);
    k_zerof<<<(N_NODES * 128 + 255) / 256, 256>>>(agg, N_NODES * 128);
    k_scatter<<<scatterBlocks, 256>>>(ei, p, agg, deg, 0);
    k_y2<<<1024, 256>>>(agg, r2, bl2, deg, y2);
    k_finalize<<<1, 1>>>(1);
    // t3 = relu(LN2(y2) @ W3 + b3)
    k_gemm<2, true, true, false><<<g3, 256>>>(y2, nullptr, W3, nullptr, b3, t3,
                                              M, 256, 128, nullptr, ln2w, ln2b, stats + 2, nullptr);
    // out = t3 @ W4 + b4
    k_gemm<0, false, true, false><<<g4, 256>>>(t3, nullptr, W4, nullptr, b4, out,
                                               M, 128, 256, nullptr, nullptr, nullptr, nullptr, nullptr);
}

// round 2
// speedup vs baseline: 1.3365x; 1.3365x over previous
#include <cuda_runtime.h>
#include <cuda_bf16.h>

#define N_NODES 50000
#define N_EDGES 800000

// ---------------- scratch (static device globals; no allocation) ----------------
static __device__ float  g_agg[(size_t)N_NODES * 128];
static __device__ float  g_deg[N_NODES];
static __device__ float  g_y1 [(size_t)N_NODES * 256];
static __device__ float  g_t1 [(size_t)N_NODES * 512];
static __device__ float  g_h2 [(size_t)N_NODES * 256];
static __device__ float  g_p  [(size_t)N_NODES * 128];
static __device__ float  g_r2 [(size_t)N_NODES * 128];
static __device__ float  g_y2 [(size_t)N_NODES * 128];
static __device__ float  g_t3 [(size_t)N_NODES * 256];
static __device__ double g_sums[4];
static __device__ float  g_stats[4];   // mu1, rsigma1, mu2, rsigma2
static __device__ int    g_is64;

// ---------------- init ----------------
__global__ void k_init(const unsigned long long* __restrict__ ei)
{
    int ok = 1;
#pragma unroll
    for (int i = 0; i < 16; i++)
        ok &= ((ei[i] >> 32) == 0ull) ? 1 : 0;
    g_is64 = ok;
    g_sums[0] = 0.0; g_sums[1] = 0.0; g_sums[2] = 0.0; g_sums[3] = 0.0;
}

__global__ void k_zerof(float* __restrict__ p, int n)
{
    int i = blockIdx.x * blockDim.x + threadIdx.x;
    if (i < n) p[i] = 0.0f;
}

// ---------------- edge scatter: warp per edge, float4 vector-RED per lane ----------------
__global__ void k_scatter(const void* __restrict__ ei, const float* __restrict__ feat,
                          float* __restrict__ agg, float* __restrict__ deg, int addDeg)
{
    int gw   = (blockIdx.x * blockDim.x + threadIdx.x) >> 5;
    int lane = threadIdx.x & 31;
    if (gw >= N_EDGES) return;

    long long s, d;
    if (g_is64) {
        const long long* p = (const long long*)ei;
        s = p[gw]; d = p[N_EDGES + gw];
    } else {
        const int* p = (const int*)ei;
        s = p[gw];  d = p[N_EDGES + gw];
    }

    float4 v = reinterpret_cast<const float4*>(feat + s * 128)[lane];
    float* dp = agg + d * 128 + lane * 4;
    asm volatile("red.global.add.v4.f32 [%0], {%1,%2,%3,%4};"
                 :: "l"(dp), "f"(v.x), "f"(v.y), "f"(v.z), "f"(v.w) : "memory");
    if (addDeg && lane == 0) atomicAdd(deg + d, 1.0f);
}

// ---------------- split-bf16 tensor-core GEMM ----------------
// C = A@B (+bias)(+relu)(+global stats), fp32 in/out, internally 3-term bf16 split:
//   A = Ah + Al, B = Bh + Bl; C ~= Ah*Bh + Ah*Bl + Al*Bh   (error ~2^-16 relative)
// Tile: 128x128, k-step 32, 256 threads = 8 warps (2m x 4n), warp tile 64x32,
// mma.sync.m16n8k16.bf16 with fp32 accum.
// AMODE 0: plain A[M,K]
// AMODE 1: conv1 dual-A (k<128: agg*inv_deg; else x), dual-B (Wl/Wr), K=256 virtual
// AMODE 2: A' = relu((A - mu) * rsigma * lnw[k] + lnb[k])
#define AS_STR 40   // padded k-stride (bf16 elems) -> 80B rows, conflict-free 16B phases

__device__ __forceinline__ void mma_bf16(float* c, const unsigned* a, const unsigned* b)
{
    asm volatile(
        "mma.sync.aligned.m16n8k16.row.col.f32.bf16.bf16.f32 "
        "{%0,%1,%2,%3}, {%4,%5,%6,%7}, {%8,%9}, {%0,%1,%2,%3};\n"
        : "+f"(c[0]), "+f"(c[1]), "+f"(c[2]), "+f"(c[3])
        : "r"(a[0]), "r"(a[1]), "r"(a[2]), "r"(a[3]), "r"(b[0]), "r"(b[1]));
}

template <int AMODE, bool RELU, bool BIAS, bool STATS>
__global__ void __launch_bounds__(256, 2)
k_gemm(const float* __restrict__ A, const float* __restrict__ A2,
       const float* __restrict__ B, const float* __restrict__ B2,
       const float* __restrict__ bias, float* __restrict__ C,
       int M, int Nc, int K,
       const float* __restrict__ deg,
       const float* __restrict__ lnw, const float* __restrict__ lnb,
       const float* __restrict__ stats, double* __restrict__ sums)
{
    __shared__ __align__(16) __nv_bfloat16 Ash[128 * AS_STR];
    __shared__ __align__(16) __nv_bfloat16 Asl[128 * AS_STR];
    __shared__ __align__(16) __nv_bfloat16 Bsh[128 * AS_STR];   // stored [n][k]
    __shared__ __align__(16) __nv_bfloat16 Bsl[128 * AS_STR];
    __shared__ double sred[256];

    const int tid  = threadIdx.x;
    const int lane = tid & 31;
    const int wid  = tid >> 5;
    const int g    = lane >> 2;
    const int t4   = lane & 3;
    const int warpM = (wid >> 2) * 64;
    const int warpN = (wid & 3) * 32;
    const int rowBase = blockIdx.y * 128;
    const int colBase = blockIdx.x * 128;

    float mu = 0.f, rs = 0.f;
    if (AMODE == 2) { mu = stats[0]; rs = stats[1]; }

    float acc[4][4][4];
#pragma unroll
    for (int i = 0; i < 4; i++)
#pragma unroll
        for (int j = 0; j < 4; j++)
#pragma unroll
            for (int k = 0; k < 4; k++) acc[i][j][k] = 0.f;

    // A loader mapping: rows aR, aR+64 ; cols aC + {0,4}
    const int aR = tid >> 2;
    const int aC = (tid & 3) * 8;
    // B loader mapping: k row bK, cols bN + {0,4,8,12}
    const int bK = tid >> 3;
    const int bN = (tid & 7) * 16;

    for (int k0 = 0; k0 < K; k0 += 32) {
        // ---- A tile -> split bf16 ----
#pragma unroll
        for (int rr = 0; rr < 2; rr++) {
            int r = aR + rr * 64;
            int grow = rowBase + r;
            float inv = 1.0f;
            if (AMODE == 1 && k0 < 128 && grow < M) inv = 1.0f / fmaxf(deg[grow], 1.0f);
#pragma unroll
            for (int cc = 0; cc < 2; cc++) {
                int c = aC + cc * 4;
                float4 v = make_float4(0.f, 0.f, 0.f, 0.f);
                if (grow < M) {
                    int k = k0 + c;
                    if (AMODE == 1) {
                        if (k < 128) {
                            v = *reinterpret_cast<const float4*>(A + (size_t)grow * 128 + k);
                            v.x *= inv; v.y *= inv; v.z *= inv; v.w *= inv;
                        } else {
                            v = *reinterpret_cast<const float4*>(A2 + (size_t)grow * 128 + (k - 128));
                        }
                    } else {
                        v = *reinterpret_cast<const float4*>(A + (size_t)grow * K + k);
                        if (AMODE == 2) {
                            float4 w4 = *reinterpret_cast<const float4*>(lnw + k);
                            float4 b4 = *reinterpret_cast<const float4*>(lnb + k);
                            v.x = fmaxf((v.x - mu) * rs * w4.x + b4.x, 0.f);
                            v.y = fmaxf((v.y - mu) * rs * w4.y + b4.y, 0.f);
                            v.z = fmaxf((v.z - mu) * rs * w4.z + b4.z, 0.f);
                            v.w = fmaxf((v.w - mu) * rs * w4.w + b4.w, 0.f);
                        }
                    }
                }
                float vv[4] = {v.x, v.y, v.z, v.w};
#pragma unroll
                for (int j = 0; j < 4; j++) {
                    __nv_bfloat16 h = __float2bfloat16_rn(vv[j]);
                    __nv_bfloat16 l = __float2bfloat16_rn(vv[j] - __bfloat162float(h));
                    Ash[r * AS_STR + c + j] = h;
                    Asl[r * AS_STR + c + j] = l;
                }
            }
        }
        // ---- B tile -> split bf16, transposed to [n][k] ----
        {
            int kg = k0 + bK;
            const float* Bp = B;
            int kk = kg;
            if (AMODE == 1 && kg >= 128) { Bp = B2; kk = kg - 128; }
#pragma unroll
            for (int cc = 0; cc < 4; cc++) {
                int n = bN + cc * 4;
                float4 v = *reinterpret_cast<const float4*>(Bp + (size_t)kk * Nc + colBase + n);
                float vv[4] = {v.x, v.y, v.z, v.w};
#pragma unroll
                for (int j = 0; j < 4; j++) {
                    __nv_bfloat16 h = __float2bfloat16_rn(vv[j]);
                    __nv_bfloat16 l = __float2bfloat16_rn(vv[j] - __bfloat162float(h));
                    Bsh[(n + j) * AS_STR + bK] = h;
                    Bsl[(n + j) * AS_STR + bK] = l;
                }
            }
        }
        __syncthreads();

        // ---- tensor-core compute ----
#pragma unroll
        for (int kh = 0; kh < 32; kh += 16) {
            unsigned Ah[4][4], Al[4][4];
#pragma unroll
            for (int mt = 0; mt < 4; mt++) {
                int r0 = warpM + mt * 16 + g;
                int cA = kh + 2 * t4;
                Ah[mt][0] = *reinterpret_cast<const unsigned*>(Ash + r0 * AS_STR + cA);
                Ah[mt][1] = *reinterpret_cast<const unsigned*>(Ash + (r0 + 8) * AS_STR + cA);
                Ah[mt][2] = *reinterpret_cast<const unsigned*>(Ash + r0 * AS_STR + cA + 8);
                Ah[mt][3] = *reinterpret_cast<const unsigned*>(Ash + (r0 + 8) * AS_STR + cA + 8);
                Al[mt][0] = *reinterpret_cast<const unsigned*>(Asl + r0 * AS_STR + cA);
                Al[mt][1] = *reinterpret_cast<const unsigned*>(Asl + (r0 + 8) * AS_STR + cA);
                Al[mt][2] = *reinterpret_cast<const unsigned*>(Asl + r0 * AS_STR + cA + 8);
                Al[mt][3] = *reinterpret_cast<const unsigned*>(Asl + (r0 + 8) * AS_STR + cA + 8);
            }
#pragma unroll
            for (int nt = 0; nt < 4; nt++) {
                int n0 = warpN + nt * 8 + g;
                int cB = kh + 2 * t4;
                unsigned Bh[2], Bl[2];
                Bh[0] = *reinterpret_cast<const unsigned*>(Bsh + n0 * AS_STR + cB);
                Bh[1] = *reinterpret_cast<const unsigned*>(Bsh + n0 * AS_STR + cB + 8);
                Bl[0] = *reinterpret_cast<const unsigned*>(Bsl + n0 * AS_STR + cB);
                Bl[1] = *reinterpret_cast<const unsigned*>(Bsl + n0 * AS_STR + cB + 8);
#pragma unroll
                for (int mt = 0; mt < 4; mt++) {
                    mma_bf16(acc[mt][nt], Ah[mt], Bh);
                    mma_bf16(acc[mt][nt], Ah[mt], Bl);
                    mma_bf16(acc[mt][nt], Al[mt], Bh);
                }
            }
        }
        __syncthreads();
    }

    // ---- epilogue ----
    double s1 = 0.0, s2 = 0.0;
#pragma unroll
    for (int nt = 0; nt < 4; nt++) {
        int col = colBase + warpN + nt * 8 + 2 * t4;
        float2 bv = make_float2(0.f, 0.f);
        if (BIAS) bv = *reinterpret_cast<const float2*>(bias + col);
#pragma unroll
        for (int mt = 0; mt < 4; mt++) {
            int r0 = rowBase + warpM + mt * 16 + g;
            float c0 = acc[mt][nt][0] + bv.x;
            float c1 = acc[mt][nt][1] + bv.y;
            float c2 = acc[mt][nt][2] + bv.x;
            float c3 = acc[mt][nt][3] + bv.y;
            if (RELU) {
                c0 = fmaxf(c0, 0.f); c1 = fmaxf(c1, 0.f);
                c2 = fmaxf(c2, 0.f); c3 = fmaxf(c3, 0.f);
            }
            if (r0 < M) {
                *reinterpret_cast<float2*>(C + (size_t)r0 * Nc + col) = make_float2(c0, c1);
                if (STATS) { s1 += (double)c0 + (double)c1;
                             s2 += (double)c0 * c0 + (double)c1 * c1; }
            }
            if (r0 + 8 < M) {
                *reinterpret_cast<float2*>(C + (size_t)(r0 + 8) * Nc + col) = make_float2(c2, c3);
                if (STATS) { s1 += (double)c2 + (double)c3;
                             s2 += (double)c2 * c2 + (double)c3 * c3; }
            }
        }
    }

    if (STATS) {
        sred[tid] = s1; __syncthreads();
        for (int o = 128; o > 0; o >>= 1) { if (tid < o) sred[tid] += sred[tid + o]; __syncthreads(); }
        if (tid == 0) atomicAdd(&sums[0], sred[0]);
        __syncthreads();
        sred[tid] = s2; __syncthreads();
        for (int o = 128; o > 0; o >>= 1) { if (tid < o) sred[tid] += sred[tid + o]; __syncthreads(); }
        if (tid == 0) atomicAdd(&sums[1], sred[0]);
    }
}

// ---------------- conv2 combine: y2 = agg/deg + bl2 + r2, with global stats ----------------
__global__ void k_y2(const float* __restrict__ agg, const float* __restrict__ r2,
                     const float* __restrict__ bl2, const float* __restrict__ deg,
                     float* __restrict__ y2)
{
    __shared__ double sred[256];
    double s1 = 0.0, s2 = 0.0;
    const int n = N_NODES * 128;
    for (int idx = blockIdx.x * blockDim.x + threadIdx.x; idx < n; idx += gridDim.x * blockDim.x) {
        int i = idx >> 7, c = idx & 127;
        float y = agg[idx] / fmaxf(deg[i], 1.0f) + bl2[c] + r2[idx];
        y2[idx] = y;
        s1 += (double)y; s2 += (double)y * (double)y;
    }
    int tid = threadIdx.x;
    sred[tid] = s1; __syncthreads();
    for (int o = 128; o > 0; o >>= 1) { if (tid < o) sred[tid] += sred[tid + o]; __syncthreads(); }
    if (tid == 0) atomicAdd(&g_sums[2], sred[0]);
    __syncthreads();
    sred[tid] = s2; __syncthreads();
    for (int o = 128; o > 0; o >>= 1) { if (tid < o) sred[tid] += sred[tid + o]; __syncthreads(); }
    if (tid == 0) atomicAdd(&g_sums[3], sred[0]);
}

__global__ void k_finalize(int stage)
{
    double cnt = (stage == 0) ? (double)N_NODES * 256.0 : (double)N_NODES * 128.0;
    int o = stage * 2;
    double mu  = g_sums[o] / cnt;
    double var = g_sums[o + 1] / cnt - mu * mu;
    g_stats[o]     = (float)mu;
    g_stats[o + 1] = (float)(1.0 / sqrt(var + 1e-5));
}

// ---------------- launch ----------------
extern "C" void kernel_launch(void* const* d_in, const int* in_sizes, int n_in,
                              void* d_out, int out_size)
{
    const float* x    = (const float*)d_in[0];
    const void*  ei   =               d_in[1];
    const float* Wl1  = (const float*)d_in[2];
    const float* bl1  = (const float*)d_in[3];
    const float* Wr1  = (const float*)d_in[4];
    const float* ln1w = (const float*)d_in[5];
    const float* ln1b = (const float*)d_in[6];
    const float* W1   = (const float*)d_in[7];
    const float* b1   = (const float*)d_in[8];
    const float* W2   = (const float*)d_in[9];
    const float* b2   = (const float*)d_in[10];
    const float* Wl2  = (const float*)d_in[11];
    const float* bl2  = (const float*)d_in[12];
    const float* Wr2  = (const float*)d_in[13];
    const float* ln2w = (const float*)d_in[14];
    const float* ln2b = (const float*)d_in[15];
    const float* W3   = (const float*)d_in[16];
    const float* b3   = (const float*)d_in[17];
    const float* W4   = (const float*)d_in[18];
    const float* b4   = (const float*)d_in[19];
    float* out = (float*)d_out;

    float *agg, *deg, *y1, *t1, *h2, *p, *r2, *y2, *t3, *stats;
    double* sums;
    cudaGetSymbolAddress((void**)&agg,  g_agg);
    cudaGetSymbolAddress((void**)&deg,  g_deg);
    cudaGetSymbolAddress((void**)&y1,   g_y1);
    cudaGetSymbolAddress((void**)&t1,   g_t1);
    cudaGetSymbolAddress((void**)&h2,   g_h2);
    cudaGetSymbolAddress((void**)&p,    g_p);
    cudaGetSymbolAddress((void**)&r2,   g_r2);
    cudaGetSymbolAddress((void**)&y2,   g_y2);
    cudaGetSymbolAddress((void**)&t3,   g_t3);
    cudaGetSymbolAddress((void**)&sums, g_sums);
    cudaGetSymbolAddress((void**)&stats, g_stats);

    const int M = N_NODES;
    const unsigned gy = (M + 127) / 128;
    dim3 g1(2, gy), g2(4, gy), g3(2, gy), g4(1, gy);
    const int scatterBlocks = (N_EDGES * 32 + 255) / 256;

    // --- conv1 ---
    k_init<<<1, 1>>>((const unsigned long long*)ei);
    k_zerof<<<(N_NODES * 128 + 255) / 256, 256>>>(agg, N_NODES * 128);
    k_zerof<<<(N_NODES + 255) / 256, 256>>>(deg, N_NODES);
    k_scatter<<<scatterBlocks, 256>>>(ei, x, agg, deg, 1);
    // y1 = (agg/deg)@Wl1 + bl1 + x@Wr1, + global stats for LN1
    k_gemm<1, false, true, true><<<g1, 256>>>(agg, x, Wl1, Wr1, bl1, y1,
                                              M, 256, 256, deg, nullptr, nullptr, nullptr, sums);
    k_finalize<<<1, 1>>>(0);
    // t1 = relu(LN1(y1) @ W1 + b1)
    k_gemm<2, true, true, false><<<g2, 256>>>(y1, nullptr, W1, nullptr, b1, t1,
                                              M, 512, 256, nullptr, ln1w, ln1b, stats + 0, nullptr);
    // h2 = relu(t1 @ W2 + b2)
    k_gemm<0, true, true, false><<<g3, 256>>>(t1, nullptr, W2, nullptr, b2, h2,
                                              M, 256, 512, nullptr, nullptr, nullptr, nullptr, nullptr);

    // --- conv2 (projected-first aggregation: agg(h)@Wl2 == agg(h@Wl2)) ---
    k_gemm<0, false, false, false><<<g4, 256>>>(h2, nullptr, Wl2, nullptr, nullptr, p,
                                                M, 128, 256, nullptr, nullptr, nullptr, nullptr, nullptr);
    k_gemm<0, false, false, false><<<g4, 256>>>(h2, nullptr, Wr2, nullptr, nullptr, r2,
                                                M, 128, 256, nullptr, nullptr, nullptr, nullptr, nullptr);
    k_zerof<<<(N_NODES * 128 + 255) / 256, 256>>>(agg, N_NODES * 128);
    k_scatter<<<scatterBlocks, 256>>>(ei, p, agg, deg, 0);
    k_y2<<<1024, 256>>>(agg, r2, bl2, deg, y2);
    k_finalize<<<1, 1>>>(1);
    // t3 = relu(LN2(y2) @ W3 + b3)
    k_gemm<2, true, true, false><<<g3, 256>>>(y2, nullptr, W3, nullptr, b3, t3,
                                              M, 256, 128, nullptr, ln2w, ln2b, stats + 2, nullptr);
    // out = t3 @ W4 + b4
    k_gemm<0, false, true, false><<<g4, 256>>>(t3, nullptr, W4, nullptr, b4, out,
                                               M, 128, 256, nullptr, nullptr, nullptr, nullptr, nullptr);
}

// round 3
// speedup vs baseline: 1.7673x; 1.3224x over previous
#include <cuda_runtime.h>
#include <cuda_bf16.h>

#define N_NODES 50000
#define N_EDGES 800000

// ---------------- scratch (static device globals; no allocation) ----------------
static __device__ float  g_agg[(size_t)N_NODES * 128];
static __device__ float  g_deg[N_NODES];
static __device__ float  g_y1 [(size_t)N_NODES * 256];
static __device__ float  g_t1 [(size_t)N_NODES * 512];
static __device__ float  g_h2 [(size_t)N_NODES * 256];
static __device__ float  g_p  [(size_t)N_NODES * 128];
static __device__ float  g_r2 [(size_t)N_NODES * 128];
static __device__ float  g_y2 [(size_t)N_NODES * 128];
static __device__ float  g_t3 [(size_t)N_NODES * 256];
static __device__ double g_sums[4];
static __device__ float  g_stats[4];   // mu1, rsigma1, mu2, rsigma2
static __device__ int    g_is64;

// ---------------- init ----------------
__global__ void k_init(const unsigned long long* __restrict__ ei)
{
    int ok = 1;
#pragma unroll
    for (int i = 0; i < 16; i++)
        ok &= ((ei[i] >> 32) == 0ull) ? 1 : 0;
    g_is64 = ok;
    g_sums[0] = 0.0; g_sums[1] = 0.0; g_sums[2] = 0.0; g_sums[3] = 0.0;
}

__global__ void k_zerof(float* __restrict__ p, int n)
{
    int i = blockIdx.x * blockDim.x + threadIdx.x;
    if (i < n) p[i] = 0.0f;
}

// ---------------- edge scatter: warp per edge, float4 vector-RED per lane ----------------
__global__ void k_scatter(const void* __restrict__ ei, const float* __restrict__ feat,
                          float* __restrict__ agg, float* __restrict__ deg, int addDeg)
{
    int gw   = (blockIdx.x * blockDim.x + threadIdx.x) >> 5;
    int lane = threadIdx.x & 31;
    if (gw >= N_EDGES) return;

    long long s, d;
    if (g_is64) {
        const long long* p = (const long long*)ei;
        s = p[gw]; d = p[N_EDGES + gw];
    } else {
        const int* p = (const int*)ei;
        s = p[gw];  d = p[N_EDGES + gw];
    }

    float4 v = reinterpret_cast<const float4*>(feat + s * 128)[lane];
    float* dp = agg + d * 128 + lane * 4;
    asm volatile("red.global.add.v4.f32 [%0], {%1,%2,%3,%4};"
                 :: "l"(dp), "f"(v.x), "f"(v.y), "f"(v.z), "f"(v.w) : "memory");
    if (addDeg && lane == 0) atomicAdd(deg + d, 1.0f);
}

// ---------------- single-pass TF32 tensor-core GEMM ----------------
// C = A@B (+bias)(+relu)(+global stats), fp32 in/out, tf32 mma.m16n8k8.
// Tile 128x128, k-step 32, 256 threads = 8 warps (2m x 4n), warp tile 64x32.
// Fragments loaded via ldmatrix.x4 (b16 trick: tf32 row of 4 u32 = 8 b16).
// AMODE 0: plain A[M,K]
// AMODE 1: conv1 dual-A (k<128: agg*inv_deg; else x), dual-B (Wl/Wr), K=256 virtual
// AMODE 2: A' = relu((A - mu) * rsigma * lnw[k] + lnb[k])
#define ASTR 36   // row stride in u32 (144B = 9*16B): ldmatrix conflict-free

__device__ __forceinline__ unsigned f2tf32(float v)
{
    unsigned u;
    asm("cvt.rna.tf32.f32 %0, %1;" : "=r"(u) : "f"(v));
    return u;
}

__device__ __forceinline__ void ldsm4(unsigned* r, unsigned addr)
{
    asm volatile("ldmatrix.sync.aligned.m8n8.x4.shared.b16 {%0,%1,%2,%3}, [%4];"
                 : "=r"(r[0]), "=r"(r[1]), "=r"(r[2]), "=r"(r[3]) : "r"(addr));
}

__device__ __forceinline__ void mma_tf32(float* c, const unsigned* a, const unsigned* b)
{
    asm volatile(
        "mma.sync.aligned.m16n8k8.row.col.f32.tf32.tf32.f32 "
        "{%0,%1,%2,%3}, {%4,%5,%6,%7}, {%8,%9}, {%0,%1,%2,%3};\n"
        : "+f"(c[0]), "+f"(c[1]), "+f"(c[2]), "+f"(c[3])
        : "r"(a[0]), "r"(a[1]), "r"(a[2]), "r"(a[3]), "r"(b[0]), "r"(b[1]));
}

template <int AMODE, bool RELU, bool BIAS, bool STATS>
__global__ void __launch_bounds__(256, 2)
k_gemm(const float* __restrict__ A, const float* __restrict__ A2,
       const float* __restrict__ B, const float* __restrict__ B2,
       const float* __restrict__ bias, float* __restrict__ C,
       int M, int Nc, int K,
       const float* __restrict__ deg,
       const float* __restrict__ lnw, const float* __restrict__ lnb,
       const float* __restrict__ stats, double* __restrict__ sums)
{
    __shared__ __align__(16) unsigned As[128 * ASTR];  // [row][k] tf32
    __shared__ __align__(16) unsigned Bs[128 * ASTR];  // [n][k]  tf32
    __shared__ double sred[256];

    const int tid  = threadIdx.x;
    const int lane = tid & 31;
    const int wid  = tid >> 5;
    const int g    = lane >> 2;
    const int t4   = lane & 3;
    const int warpM = (wid >> 2) * 64;
    const int warpN = (wid & 3) * 32;
    const int rowBase = blockIdx.y * 128;
    const int colBase = blockIdx.x * 128;

    float mu = 0.f, rs = 0.f;
    if (AMODE == 2) { mu = stats[0]; rs = stats[1]; }

    float acc[4][4][4];
#pragma unroll
    for (int i = 0; i < 4; i++)
#pragma unroll
        for (int j = 0; j < 4; j++)
#pragma unroll
            for (int k = 0; k < 4; k++) acc[i][j][k] = 0.f;

    // A fill mapping: r = tid>>2 (+64), k = (tid&3)*8 + cc*4
    const int aR = tid >> 2;
    const int aK = (tid & 3) * 8;
    // B fill mapping (reg transpose): k0 = (tid&7)*4, n0 = (tid>>3)*4
    const int bK0 = (tid & 7) * 4;
    const int bN0 = (tid >> 3) * 4;

    // ldmatrix lane base addresses
    unsigned aSm = (unsigned)__cvta_generic_to_shared(As);
    unsigned bSm = (unsigned)__cvta_generic_to_shared(Bs);
    const unsigned aBase = aSm + (((warpM + (lane & 7) + ((lane >> 3) & 1) * 8) * ASTR)
                                  + ((lane >> 4) & 1) * 4) * 4u;
    const unsigned bBase = bSm + (((warpN + (lane & 7)) * ASTR) + (lane >> 3) * 4) * 4u;

    for (int k0 = 0; k0 < K; k0 += 32) {
        // ---- A tile fill ----
#pragma unroll
        for (int rr = 0; rr < 2; rr++) {
            int r = aR + rr * 64;
            int grow = rowBase + r;
            float inv = 1.0f;
            if (AMODE == 1 && k0 < 128 && grow < M) inv = 1.0f / fmaxf(deg[grow], 1.0f);
#pragma unroll
            for (int cc = 0; cc < 2; cc++) {
                int c = aK + cc * 4;
                float4 v = make_float4(0.f, 0.f, 0.f, 0.f);
                if (grow < M) {
                    int k = k0 + c;
                    if (AMODE == 1) {
                        if (k < 128) {
                            v = *reinterpret_cast<const float4*>(A + (size_t)grow * 128 + k);
                            v.x *= inv; v.y *= inv; v.z *= inv; v.w *= inv;
                        } else {
                            v = *reinterpret_cast<const float4*>(A2 + (size_t)grow * 128 + (k - 128));
                        }
                    } else {
                        v = *reinterpret_cast<const float4*>(A + (size_t)grow * K + k);
                        if (AMODE == 2) {
                            float4 w4 = *reinterpret_cast<const float4*>(lnw + k);
                            float4 b4 = *reinterpret_cast<const float4*>(lnb + k);
                            v.x = fmaxf((v.x - mu) * rs * w4.x + b4.x, 0.f);
                            v.y = fmaxf((v.y - mu) * rs * w4.y + b4.y, 0.f);
                            v.z = fmaxf((v.z - mu) * rs * w4.z + b4.z, 0.f);
                            v.w = fmaxf((v.w - mu) * rs * w4.w + b4.w, 0.f);
                        }
                    }
                }
                uint4 t;
                t.x = f2tf32(v.x); t.y = f2tf32(v.y); t.z = f2tf32(v.z); t.w = f2tf32(v.w);
                *reinterpret_cast<uint4*>(&As[r * ASTR + c]) = t;
            }
        }
        // ---- B tile fill (register transpose to [n][k]) ----
        {
            float4 row[4];
#pragma unroll
            for (int i = 0; i < 4; i++) {
                int kg = k0 + bK0 + i;
                const float* Bp = B;
                int kk = kg;
                if (AMODE == 1 && kg >= 128) { Bp = B2; kk = kg - 128; }
                row[i] = *reinterpret_cast<const float4*>(Bp + (size_t)kk * Nc + colBase + bN0);
            }
            const float* rf = reinterpret_cast<const float*>(row);
#pragma unroll
            for (int j = 0; j < 4; j++) {
                uint4 t;
                t.x = f2tf32(rf[0 * 4 + j]);
                t.y = f2tf32(rf[1 * 4 + j]);
                t.z = f2tf32(rf[2 * 4 + j]);
                t.w = f2tf32(rf[3 * 4 + j]);
                *reinterpret_cast<uint4*>(&Bs[(bN0 + j) * ASTR + bK0]) = t;
            }
        }
        __syncthreads();

        // ---- tensor-core compute: 4 k8 slices ----
#pragma unroll
        for (int kbp = 0; kbp < 2; kbp++) {
            unsigned bf[4][4];
#pragma unroll
            for (int nt = 0; nt < 4; nt++)
                ldsm4(bf[nt], bBase + (unsigned)((nt * 8 * ASTR + kbp * 16) * 4));
#pragma unroll
            for (int kk = 0; kk < 2; kk++) {
                int kb = kbp * 2 + kk;
                unsigned af[4][4];
#pragma unroll
                for (int mt = 0; mt < 4; mt++)
                    ldsm4(af[mt], aBase + (unsigned)((mt * 16 * ASTR + kb * 8) * 4));
#pragma unroll
                for (int nt = 0; nt < 4; nt++)
#pragma unroll
                    for (int mt = 0; mt < 4; mt++)
                        mma_tf32(acc[mt][nt], af[mt], &bf[nt][kk * 2]);
            }
        }
        __syncthreads();
    }

    // ---- epilogue ----
    double s1 = 0.0, s2 = 0.0;
#pragma unroll
    for (int nt = 0; nt < 4; nt++) {
        int col = colBase + warpN + nt * 8 + 2 * t4;
        float2 bv = make_float2(0.f, 0.f);
        if (BIAS) bv = *reinterpret_cast<const float2*>(bias + col);
#pragma unroll
        for (int mt = 0; mt < 4; mt++) {
            int r0 = rowBase + warpM + mt * 16 + g;
            float c0 = acc[mt][nt][0] + bv.x;
            float c1 = acc[mt][nt][1] + bv.y;
            float c2 = acc[mt][nt][2] + bv.x;
            float c3 = acc[mt][nt][3] + bv.y;
            if (RELU) {
                c0 = fmaxf(c0, 0.f); c1 = fmaxf(c1, 0.f);
                c2 = fmaxf(c2, 0.f); c3 = fmaxf(c3, 0.f);
            }
            if (r0 < M) {
                *reinterpret_cast<float2*>(C + (size_t)r0 * Nc + col) = make_float2(c0, c1);
                if (STATS) { s1 += (double)c0 + (double)c1;
                             s2 += (double)c0 * c0 + (double)c1 * c1; }
            }
            if (r0 + 8 < M) {
                *reinterpret_cast<float2*>(C + (size_t)(r0 + 8) * Nc + col) = make_float2(c2, c3);
                if (STATS) { s1 += (double)c2 + (double)c3;
                             s2 += (double)c2 * c2 + (double)c3 * c3; }
            }
        }
    }

    if (STATS) {
        sred[tid] = s1; __syncthreads();
        for (int o = 128; o > 0; o >>= 1) { if (tid < o) sred[tid] += sred[tid + o]; __syncthreads(); }
        if (tid == 0) atomicAdd(&sums[0], sred[0]);
        __syncthreads();
        sred[tid] = s2; __syncthreads();
        for (int o = 128; o > 0; o >>= 1) { if (tid < o) sred[tid] += sred[tid + o]; __syncthreads(); }
        if (tid == 0) atomicAdd(&sums[1], sred[0]);
    }
}

// ---------------- conv2 combine: y2 = agg/deg + bl2 + r2, with global stats ----------------
__global__ void k_y2(const float* __restrict__ agg, const float* __restrict__ r2,
                     const float* __restrict__ bl2, const float* __restrict__ deg,
                     float* __restrict__ y2)
{
    __shared__ double sred[256];
    double s1 = 0.0, s2 = 0.0;
    const int n = N_NODES * 128;
    for (int idx = blockIdx.x * blockDim.x + threadIdx.x; idx < n; idx += gridDim.x * blockDim.x) {
        int i = idx >> 7, c = idx & 127;
        float y = agg[idx] / fmaxf(deg[i], 1.0f) + bl2[c] + r2[idx];
        y2[idx] = y;
        s1 += (double)y; s2 += (double)y * (double)y;
    }
    int tid = threadIdx.x;
    sred[tid] = s1; __syncthreads();
    for (int o = 128; o > 0; o >>= 1) { if (tid < o) sred[tid] += sred[tid + o]; __syncthreads(); }
    if (tid == 0) atomicAdd(&g_sums[2], sred[0]);
    __syncthreads();
    sred[tid] = s2; __syncthreads();
    for (int o = 128; o > 0; o >>= 1) { if (tid < o) sred[tid] += sred[tid + o]; __syncthreads(); }
    if (tid == 0) atomicAdd(&g_sums[3], sred[0]);
}

__global__ void k_finalize(int stage)
{
    double cnt = (stage == 0) ? (double)N_NODES * 256.0 : (double)N_NODES * 128.0;
    int o = stage * 2;
    double mu  = g_sums[o] / cnt;
    double var = g_sums[o + 1] / cnt - mu * mu;
    g_stats[o]     = (float)mu;
    g_stats[o + 1] = (float)(1.0 / sqrt(var + 1e-5));
}

// ---------------- launch ----------------
extern "C" void kernel_launch(void* const* d_in, const int* in_sizes, int n_in,
                              void* d_out, int out_size)
{
    const float* x    = (const float*)d_in[0];
    const void*  ei   =               d_in[1];
    const float* Wl1  = (const float*)d_in[2];
    const float* bl1  = (const float*)d_in[3];
    const float* Wr1  = (const float*)d_in[4];
    const float* ln1w = (const float*)d_in[5];
    const float* ln1b = (const float*)d_in[6];
    const float* W1   = (const float*)d_in[7];
    const float* b1   = (const float*)d_in[8];
    const float* W2   = (const float*)d_in[9];
    const float* b2   = (const float*)d_in[10];
    const float* Wl2  = (const float*)d_in[11];
    const float* bl2  = (const float*)d_in[12];
    const float* Wr2  = (const float*)d_in[13];
    const float* ln2w = (const float*)d_in[14];
    const float* ln2b = (const float*)d_in[15];
    const float* W3   = (const float*)d_in[16];
    const float* b3   = (const float*)d_in[17];
    const float* W4   = (const float*)d_in[18];
    const float* b4   = (const float*)d_in[19];
    float* out = (float*)d_out;

    float *agg, *deg, *y1, *t1, *h2, *p, *r2, *y2, *t3, *stats;
    double* sums;
    cudaGetSymbolAddress((void**)&agg,  g_agg);
    cudaGetSymbolAddress((void**)&deg,  g_deg);
    cudaGetSymbolAddress((void**)&y1,   g_y1);
    cudaGetSymbolAddress((void**)&t1,   g_t1);
    cudaGetSymbolAddress((void**)&h2,   g_h2);
    cudaGetSymbolAddress((void**)&p,    g_p);
    cudaGetSymbolAddress((void**)&r2,   g_r2);
    cudaGetSymbolAddress((void**)&y2,   g_y2);
    cudaGetSymbolAddress((void**)&t3,   g_t3);
    cudaGetSymbolAddress((void**)&sums, g_sums);
    cudaGetSymbolAddress((void**)&stats, g_stats);

    const int M = N_NODES;
    const unsigned gy = (M + 127) / 128;
    dim3 g1(2, gy), g2(4, gy), g3(2, gy), g4(1, gy);
    const int scatterBlocks = (N_EDGES * 32 + 255) / 256;

    // --- conv1 ---
    k_init<<<1, 1>>>((const unsigned long long*)ei);
    k_zerof<<<(N_NODES * 128 + 255) / 256, 256>>>(agg, N_NODES * 128);
    k_zerof<<<(N_NODES + 255) / 256, 256>>>(deg, N_NODES);
    k_scatter<<<scatterBlocks, 256>>>(ei, x, agg, deg, 1);
    // y1 = (agg/deg)@Wl1 + bl1 + x@Wr1, + global stats for LN1
    k_gemm<1, false, true, true><<<g1, 256>>>(agg, x, Wl1, Wr1, bl1, y1,
                                              M, 256, 256, deg, nullptr, nullptr, nullptr, sums);
    k_finalize<<<1, 1>>>(0);
    // t1 = relu(LN1(y1) @ W1 + b1)
    k_gemm<2, true, true, false><<<g2, 256>>>(y1, nullptr, W1, nullptr, b1, t1,
                                              M, 512, 256, nullptr, ln1w, ln1b, stats + 0, nullptr);
    // h2 = relu(t1 @ W2 + b2)
    k_gemm<0, true, true, false><<<g3, 256>>>(t1, nullptr, W2, nullptr, b2, h2,
                                              M, 256, 512, nullptr, nullptr, nullptr, nullptr, nullptr);

    // --- conv2 (projected-first aggregation: agg(h)@Wl2 == agg(h@Wl2)) ---
    k_gemm<0, false, false, false><<<g4, 256>>>(h2, nullptr, Wl2, nullptr, nullptr, p,
                                                M, 128, 256, nullptr, nullptr, nullptr, nullptr, nullptr);
    k_gemm<0, false, false, false><<<g4, 256>>>(h2, nullptr, Wr2, nullptr, nullptr, r2,
                                                M, 128, 256, nullptr, nullptr, nullptr, nullptr, nullptr);
    k_zerof<<<(N_NODES * 128 + 255) / 256, 256>>>(agg, N_NODES * 128);
    k_scatter<<<scatterBlocks, 256>>>(ei, p, agg, deg, 0);
    k_y2<<<1024, 256>>>(agg, r2, bl2, deg, y2);
    k_finalize<<<1, 1>>>(1);
    // t3 = relu(LN2(y2) @ W3 + b3)
    k_gemm<2, true, true, false><<<g3, 256>>>(y2, nullptr, W3, nullptr, b3, t3,
                                              M, 256, 128, nullptr, ln2w, ln2b, stats + 2, nullptr);
    // out = t3 @ W4 + b4
    k_gemm<0, false, true, false><<<g4, 256>>>(t3, nullptr, W4, nullptr, b4, out,
                                               M, 128, 256, nullptr, nullptr, nullptr, nullptr, nullptr);
}